// round 2
// baseline (speedup 1.0000x reference)
#include <cuda_runtime.h>

// Problem constants (fixed by the dataset)
#define BB   8
#define LL   1024
#define HH   8
#define EE   64
#define HIST 512

#define TQ 64
#define TS 64
#define PSTR 68          // padded stride for K/P shared tile

#define SMEM_FLOATS (64*64 + 64*PSTR + 64*64 + 3*64)
#define SMEM_BYTES  (SMEM_FLOATS * 4)

__global__ __launch_bounds__(256, 2)
void ftc_attn_kernel(const float* __restrict__ q,  const float* __restrict__ k,
                     const float* __restrict__ v,  const float* __restrict__ qd,
                     const float* __restrict__ kd, const float* __restrict__ vd,
                     float* __restrict__ out)
{
    extern __shared__ float sm[];
    float* Qs = sm;                 // [e][r]  64 x 64, pre-scaled by 1/sqrt(E)
    float* KP = Qs + 64*64;         // K as [e][s] stride 68;  then P as [s][r] stride 68
    float* Vs = KP + 64*PSTR;       // [s][d]  64 x 64
    float* mrow = Vs + 64*64;       // [64] running max
    float* lrow = mrow + 64;        // [64] running sum
    float* crow = lrow + 64;        // [64] per-tile correction factor

    const int tid = threadIdx.x;
    const int ty  = tid >> 4;       // 0..15
    const int tx  = tid & 15;       // 0..15
    const int r0  = ty * 4;         // query rows owned (4)
    const int c0  = tx * 4;         // s-cols / d-dims owned (4)

    const int qt = 15 - blockIdx.x;     // big tiles launch first (load balance)
    const int bh = blockIdx.y;
    const int b  = bh >> 3;
    const int h  = bh & 7;
    const int l0 = qt * TQ;
    const bool drawn = (l0 >= HIST);
    const float scale = 0.125f;     // 1/sqrt(64)

    // element index: ((b*LL + l)*HH + h)*EE + e  =  hb + l*(HH*EE) + e
    const int hb = (b * LL * HH + h) * EE;

    // ---- load Q tile (scaled), transposed to [e][r] ----
    {
        const float* Qsrc = drawn ? qd : q;
        const int r  = tid & 63;
        const int e4 = (tid >> 6) * 16;
        const float4* src = (const float4*)(Qsrc + hb + (l0 + r) * (HH*EE) + e4);
        #pragma unroll
        for (int i = 0; i < 4; i++) {
            float4 t = src[i];
            int e = e4 + 4*i;
            Qs[(e+0)*64 + r] = t.x * scale;
            Qs[(e+1)*64 + r] = t.y * scale;
            Qs[(e+2)*64 + r] = t.z * scale;
            Qs[(e+3)*64 + r] = t.w * scale;
        }
    }
    if (tid < 64) { mrow[tid] = -3.0e38f; lrow[tid] = 0.0f; }

    float O[4][4] = {};

    for (int st = 0; st <= qt; st++) {
        const bool diag = (st == qt);
        const int  s0   = st * TS;

        __syncthreads();   // previous tile's P/V reads done

        // ---- load K tile transposed [e][s], V tile natural [s][d] ----
        {
            const int s  = tid & 63;
            const int e4 = (tid >> 6) * 16;
            const float4* ksrc = (const float4*)(k + hb + (s0 + s) * (HH*EE) + e4);
            #pragma unroll
            for (int i = 0; i < 4; i++) {
                float4 t = ksrc[i];
                int e = e4 + 4*i;
                KP[(e+0)*PSTR + s] = t.x;
                KP[(e+1)*PSTR + s] = t.y;
                KP[(e+2)*PSTR + s] = t.z;
                KP[(e+3)*PSTR + s] = t.w;
            }
        }
        {
            const int s = tid >> 2;
            const int c = (tid & 3) * 16;
            const float4* vsrc = (const float4*)(v + hb + (s0 + s) * (HH*EE) + c);
            float4* vdst = (float4*)(Vs + s*64 + c);
            #pragma unroll
            for (int i = 0; i < 4; i++) vdst[i] = vsrc[i];
        }
        __syncthreads();

        // ---- S = (Q*scale) @ K^T  (4x4 register tile) ----
        float S[4][4] = {};
        #pragma unroll 8
        for (int e = 0; e < 64; e++) {
            float4 a  = *(const float4*)&Qs[e*64   + r0];
            float4 bb = *(const float4*)&KP[e*PSTR + c0];
            S[0][0] += a.x*bb.x; S[0][1] += a.x*bb.y; S[0][2] += a.x*bb.z; S[0][3] += a.x*bb.w;
            S[1][0] += a.y*bb.x; S[1][1] += a.y*bb.y; S[1][2] += a.y*bb.z; S[1][3] += a.y*bb.w;
            S[2][0] += a.z*bb.x; S[2][1] += a.z*bb.y; S[2][2] += a.z*bb.z; S[2][3] += a.z*bb.w;
            S[3][0] += a.w*bb.x; S[3][1] += a.w*bb.y; S[3][2] += a.w*bb.z; S[3][3] += a.w*bb.w;
        }

        // causal mask on the diagonal tile (s_local > r_local)
        if (diag) {
            #pragma unroll
            for (int i = 0; i < 4; i++)
                #pragma unroll
                for (int j = 0; j < 4; j++)
                    if (c0 + j > r0 + i) S[i][j] = -1.0e30f;
        }

        __syncthreads();   // everyone done reading K; safe to overwrite with P

        // store raw scores as P-layout [s][r]
        #pragma unroll
        for (int j = 0; j < 4; j++)
            *(float4*)&KP[(c0+j)*PSTR + r0] =
                make_float4(S[0][j], S[1][j], S[2][j], S[3][j]);
        __syncthreads();

        // ---- diagonal score override: S[l][l] = dot(q_eff[l]*scale, kd[l]) ----
        if (diag && drawn) {
            const int rr = tid >> 2;
            const int c  = tid & 3;
            const float* kdr = kd + hb + (l0 + rr) * (HH*EE);
            float p = 0.0f;
            #pragma unroll
            for (int e = 0; e < 16; e++) {
                int ee = c*16 + e;
                p += Qs[ee*64 + rr] * kdr[ee];
            }
            p += __shfl_down_sync(0xffffffffu, p, 2);
            p += __shfl_down_sync(0xffffffffu, p, 1);
            if (c == 0) KP[rr*PSTR + rr] = p;
            __syncthreads();
        }

        // ---- online softmax over this tile (4 lanes per row) ----
        {
            const int rr = tid >> 2;
            const int c  = tid & 3;
            const float m_old = mrow[rr];
            float tmax = -3.0e38f;
            #pragma unroll
            for (int j = 0; j < 16; j++) {
                float x = KP[(j*4 + c)*PSTR + rr];
                tmax = fmaxf(tmax, x);
            }
            tmax = fmaxf(tmax, __shfl_down_sync(0xffffffffu, tmax, 2));
            tmax = fmaxf(tmax, __shfl_down_sync(0xffffffffu, tmax, 1));
            tmax = __shfl_sync(0xffffffffu, tmax, (tid & 31) & ~3);
            const float m_new = fmaxf(m_old, tmax);
            float sum = 0.0f;
            #pragma unroll
            for (int j = 0; j < 16; j++) {
                int idx = (j*4 + c)*PSTR + rr;
                float p = __expf(KP[idx] - m_new);
                KP[idx] = p;
                sum += p;
            }
            sum += __shfl_down_sync(0xffffffffu, sum, 2);
            sum += __shfl_down_sync(0xffffffffu, sum, 1);
            if (c == 0) {
                float corr = __expf(m_old - m_new);
                crow[rr] = corr;
                lrow[rr] = lrow[rr] * corr + sum;
                mrow[rr] = m_new;
            }
        }
        __syncthreads();

        // ---- rescale accumulators, then O += P @ V ----
        {
            float cf[4];
            #pragma unroll
            for (int i = 0; i < 4; i++) cf[i] = crow[r0 + i];
            #pragma unroll
            for (int i = 0; i < 4; i++)
                #pragma unroll
                for (int j = 0; j < 4; j++) O[i][j] *= cf[i];
        }
        #pragma unroll 8
        for (int s = 0; s < 64; s++) {
            float4 p  = *(const float4*)&KP[s*PSTR + r0];
            float4 vv = *(const float4*)&Vs[s*64  + c0];
            O[0][0] += p.x*vv.x; O[0][1] += p.x*vv.y; O[0][2] += p.x*vv.z; O[0][3] += p.x*vv.w;
            O[1][0] += p.y*vv.x; O[1][1] += p.y*vv.y; O[1][2] += p.y*vv.z; O[1][3] += p.y*vv.w;
            O[2][0] += p.z*vv.x; O[2][1] += p.z*vv.y; O[2][2] += p.z*vv.z; O[2][3] += p.z*vv.w;
            O[3][0] += p.w*vv.x; O[3][1] += p.w*vv.y; O[3][2] += p.w*vv.z; O[3][3] += p.w*vv.w;
        }

        // ---- diagonal value correction: O[l] += P[l][l] * (vd[l] - v[l]) ----
        if (diag && drawn) {
            #pragma unroll
            for (int i = 0; i < 4; i++) {
                const int rl = r0 + i;
                const float pll = KP[rl*PSTR + rl];
                const int base = hb + (l0 + rl) * (HH*EE) + c0;
                float4 dv = *(const float4*)(vd + base);
                float4 ov = *(const float4*)(v  + base);
                O[i][0] += pll * (dv.x - ov.x);
                O[i][1] += pll * (dv.y - ov.y);
                O[i][2] += pll * (dv.z - ov.z);
                O[i][3] += pll * (dv.w - ov.w);
            }
        }
    }

    // ---- epilogue: normalize and store ----
    #pragma unroll
    for (int i = 0; i < 4; i++) {
        const float inv = 1.0f / lrow[r0 + i];
        const int base = hb + (l0 + r0 + i) * (HH*EE) + c0;
        *(float4*)(out + base) =
            make_float4(O[i][0]*inv, O[i][1]*inv, O[i][2]*inv, O[i][3]*inv);
    }
}

extern "C" void kernel_launch(void* const* d_in, const int* in_sizes, int n_in,
                              void* d_out, int out_size)
{
    const float* q  = (const float*)d_in[0];
    const float* k  = (const float*)d_in[1];
    const float* v  = (const float*)d_in[2];
    const float* qd = (const float*)d_in[3];
    const float* kd = (const float*)d_in[4];
    const float* vd = (const float*)d_in[5];
    // d_in[6] = attn_mask (exactly triu(k=1) -> handled analytically)
    // d_in[7] = history_len (fixed 512)
    float* out = (float*)d_out;

    cudaFuncSetAttribute(ftc_attn_kernel,
                         cudaFuncAttributeMaxDynamicSharedMemorySize, SMEM_BYTES);
    dim3 grid(16, BB * HH);   // 16 q-tiles x 64 heads
    ftc_attn_kernel<<<grid, 256, SMEM_BYTES>>>(q, k, v, qd, kd, vd, out);
}

// round 3
// speedup vs baseline: 2.5080x; 2.5080x over previous
#include <cuda_runtime.h>
#include <cstdint>

// Problem constants
#define BB   8
#define LL   1024
#define HH   8
#define EE   64
#define HIST 512
#define RSTR 512          // element stride between consecutive l (HH*EE)

#define SSTR 68           // smem row stride in floats (pad 4)
#define SM_K 0
#define SM_V (64*SSTR)
#define SM_P (2*64*SSTR)
#define SM_D (3*64*SSTR)
#define SMEM_FLOATS (3*64*SSTR + 64)
#define SMEM_BYTES  (SMEM_FLOATS * 4)

static __device__ __forceinline__ uint32_t f2tf(float f) {
    uint32_t u;
    asm("cvt.rna.tf32.f32 %0, %1;" : "=r"(u) : "f"(f));
    return u;
}

static __device__ __forceinline__ void mma8(float* c, const uint32_t* a,
                                            uint32_t b0, uint32_t b1) {
    asm volatile("mma.sync.aligned.m16n8k8.row.col.f32.tf32.tf32.f32 "
                 "{%0,%1,%2,%3}, {%4,%5,%6,%7}, {%8,%9}, {%0,%1,%2,%3};"
                 : "+f"(c[0]), "+f"(c[1]), "+f"(c[2]), "+f"(c[3])
                 : "r"(a[0]), "r"(a[1]), "r"(a[2]), "r"(a[3]),
                   "r"(b0), "r"(b1));
}

__global__ __launch_bounds__(128, 3)
void ftc_attn_tc(const float* __restrict__ q,  const float* __restrict__ k,
                 const float* __restrict__ v,  const float* __restrict__ qd,
                 const float* __restrict__ kd, const float* __restrict__ vd,
                 float* __restrict__ out)
{
    extern __shared__ float sm[];

    const int tid  = threadIdx.x;
    const int warp = tid >> 5;
    const int lane = tid & 31;
    const int g    = lane >> 2;     // groupID (row within frag)
    const int tig  = lane & 3;      // thread in group

    const int qt = 15 - blockIdx.x;       // big tiles first
    const int bh = blockIdx.y;
    const int b  = bh >> 3;
    const int h  = bh & 7;
    const int l0 = qt * 64;
    const bool drawn = (l0 >= HIST);
    const int hb = (b * LL * HH + h) * EE;

    const int lr0 = warp * 16 + g;        // local row (c0/c1)
    const int lr1 = lr0 + 8;              // local row (c2/c3)
    const int grow0 = l0 + lr0;
    const int grow1 = l0 + lr1;

    // ---- Q fragments: load once, scale by 1/8, round to tf32 ----
    const float* Qsrc = drawn ? qd : q;
    const float* q0p = Qsrc + hb + grow0 * RSTR;
    const float* q1p = Qsrc + hb + grow1 * RSTR;
    uint32_t qf[8][4];
    #pragma unroll
    for (int kf = 0; kf < 8; kf++) {
        const int c = kf * 8 + tig;
        qf[kf][0] = f2tf(q0p[c]     * 0.125f);
        qf[kf][1] = f2tf(q1p[c]     * 0.125f);
        qf[kf][2] = f2tf(q0p[c + 4] * 0.125f);
        qf[kf][3] = f2tf(q1p[c + 4] * 0.125f);
    }

    float O[8][4];
    #pragma unroll
    for (int nf = 0; nf < 8; nf++) {
        O[nf][0] = 0.f; O[nf][1] = 0.f; O[nf][2] = 0.f; O[nf][3] = 0.f;
    }
    float m0 = -1e30f, m1 = -1e30f;     // running row max
    float rl0 = 0.f,  rl1 = 0.f;        // running row sum

    for (int st = 0; st <= qt; st++) {
        const int  s0   = st * 64;
        const bool diag = (st == qt);

        __syncthreads();   // previous tile smem consumers done

        // ---- K tile -> Ks[s][e] (tf32-rounded), coalesced ----
        #pragma unroll
        for (int it = 0; it < 8; it++) {
            const int i  = it * 128 + tid;
            const int s  = i >> 4;
            const int e4 = (i & 15) * 4;
            const float4 t = *(const float4*)(k + hb + (s0 + s) * RSTR + e4);
            float* d = sm + SM_K + s * SSTR + e4;
            d[0] = __uint_as_float(f2tf(t.x));
            d[1] = __uint_as_float(f2tf(t.y));
            d[2] = __uint_as_float(f2tf(t.z));
            d[3] = __uint_as_float(f2tf(t.w));
        }
        // ---- V tile -> Vt[d][s] transposed (tf32-rounded) ----
        {
            const int s     = tid & 63;
            const int dbase = (tid >> 6) * 32;
            const float* vp = v + hb + (s0 + s) * RSTR + dbase;
            #pragma unroll
            for (int i = 0; i < 8; i++) {
                const float4 t = *(const float4*)(vp + i * 4);
                float* d = sm + SM_V + (dbase + i * 4) * SSTR + s;
                d[0*SSTR] = __uint_as_float(f2tf(t.x));
                d[1*SSTR] = __uint_as_float(f2tf(t.y));
                d[2*SSTR] = __uint_as_float(f2tf(t.z));
                d[3*SSTR] = __uint_as_float(f2tf(t.w));
            }
        }
        // ---- diagonal scores (drawn): sd[l] = dot(qd[l], kd[l]) / 8 ----
        if (diag && drawn) {
            const int lr  = tid >> 1;
            const int off = (tid & 1) * 32;
            const float* qp = qd + hb + (l0 + lr) * RSTR + off;
            const float* kp = kd + hb + (l0 + lr) * RSTR + off;
            float acc = 0.f;
            #pragma unroll
            for (int i = 0; i < 8; i++) {
                const float4 a = *(const float4*)(qp + i * 4);
                const float4 c = *(const float4*)(kp + i * 4);
                acc += a.x*c.x + a.y*c.y + a.z*c.z + a.w*c.w;
            }
            acc += __shfl_xor_sync(0xffffffffu, acc, 1);
            if (!(tid & 1)) sm[SM_D + lr] = acc * 0.125f;
        }
        __syncthreads();

        // ---- S = Q @ K^T via tensor cores ----
        float S[8][4];
        #pragma unroll
        for (int nf = 0; nf < 8; nf++) {
            S[nf][0] = 0.f; S[nf][1] = 0.f; S[nf][2] = 0.f; S[nf][3] = 0.f;
        }
        #pragma unroll
        for (int kf = 0; kf < 8; kf++) {
            #pragma unroll
            for (int nf = 0; nf < 8; nf++) {
                const float* kb = sm + SM_K + (nf * 8 + g) * SSTR + kf * 8 + tig;
                mma8(S[nf], qf[kf],
                     __float_as_uint(kb[0]), __float_as_uint(kb[4]));
            }
        }

        // ---- mask + diagonal override (diag tile only) ----
        if (diag) {
            #pragma unroll
            for (int nf = 0; nf < 8; nf++) {
                const int sc = s0 + nf * 8 + 2 * tig;
                if (sc     > grow0) S[nf][0] = -1e30f;
                if (sc + 1 > grow0) S[nf][1] = -1e30f;
                if (sc     > grow1) S[nf][2] = -1e30f;
                if (sc + 1 > grow1) S[nf][3] = -1e30f;
                if (drawn) {
                    if (sc     == grow0) S[nf][0] = sm[SM_D + lr0];
                    if (sc + 1 == grow0) S[nf][1] = sm[SM_D + lr0];
                    if (sc     == grow1) S[nf][2] = sm[SM_D + lr1];
                    if (sc + 1 == grow1) S[nf][3] = sm[SM_D + lr1];
                }
            }
        }

        // ---- online softmax (per-warp, rows in registers) ----
        float tm0 = -1e30f, tm1 = -1e30f;
        #pragma unroll
        for (int nf = 0; nf < 8; nf++) {
            tm0 = fmaxf(tm0, fmaxf(S[nf][0], S[nf][1]));
            tm1 = fmaxf(tm1, fmaxf(S[nf][2], S[nf][3]));
        }
        tm0 = fmaxf(tm0, __shfl_xor_sync(0xffffffffu, tm0, 1));
        tm0 = fmaxf(tm0, __shfl_xor_sync(0xffffffffu, tm0, 2));
        tm1 = fmaxf(tm1, __shfl_xor_sync(0xffffffffu, tm1, 1));
        tm1 = fmaxf(tm1, __shfl_xor_sync(0xffffffffu, tm1, 2));
        const float mn0 = fmaxf(m0, tm0);
        const float mn1 = fmaxf(m1, tm1);
        const float corr0 = __expf(m0 - mn0);
        const float corr1 = __expf(m1 - mn1);
        m0 = mn0; m1 = mn1;

        float sum0 = 0.f, sum1 = 0.f;
        #pragma unroll
        for (int nf = 0; nf < 8; nf++) {
            S[nf][0] = __expf(S[nf][0] - mn0); sum0 += S[nf][0];
            S[nf][1] = __expf(S[nf][1] - mn0); sum0 += S[nf][1];
            S[nf][2] = __expf(S[nf][2] - mn1); sum1 += S[nf][2];
            S[nf][3] = __expf(S[nf][3] - mn1); sum1 += S[nf][3];
        }
        sum0 += __shfl_xor_sync(0xffffffffu, sum0, 1);
        sum0 += __shfl_xor_sync(0xffffffffu, sum0, 2);
        sum1 += __shfl_xor_sync(0xffffffffu, sum1, 1);
        sum1 += __shfl_xor_sync(0xffffffffu, sum1, 2);
        rl0 = rl0 * corr0 + sum0;
        rl1 = rl1 * corr1 + sum1;

        #pragma unroll
        for (int nf = 0; nf < 8; nf++) {
            O[nf][0] *= corr0; O[nf][1] *= corr0;
            O[nf][2] *= corr1; O[nf][3] *= corr1;
        }

        // ---- capture diagonal p (full precision) for value correction ----
        if (diag && drawn) {
            #pragma unroll
            for (int nf = 0; nf < 8; nf++) {
                const int sc = s0 + nf * 8 + 2 * tig;
                if (sc     == grow0) sm[SM_D + lr0] = S[nf][0];
                if (sc + 1 == grow0) sm[SM_D + lr0] = S[nf][1];
                if (sc     == grow1) sm[SM_D + lr1] = S[nf][2];
                if (sc + 1 == grow1) sm[SM_D + lr1] = S[nf][3];
            }
        }

        // ---- store P (tf32) to warp-private rows of Ps ----
        #pragma unroll
        for (int nf = 0; nf < 8; nf++) {
            uint32_t* p0 = (uint32_t*)(sm + SM_P + lr0 * SSTR + nf * 8 + 2 * tig);
            uint32_t* p1 = (uint32_t*)(sm + SM_P + lr1 * SSTR + nf * 8 + 2 * tig);
            p0[0] = f2tf(S[nf][0]); p0[1] = f2tf(S[nf][1]);
            p1[0] = f2tf(S[nf][2]); p1[1] = f2tf(S[nf][3]);
        }
        __syncwarp();

        // ---- O += P @ V via tensor cores ----
        #pragma unroll
        for (int kf = 0; kf < 8; kf++) {
            uint32_t a[4];
            const float* pa0 = sm + SM_P + lr0 * SSTR + kf * 8 + tig;
            const float* pa1 = sm + SM_P + lr1 * SSTR + kf * 8 + tig;
            a[0] = __float_as_uint(pa0[0]);
            a[1] = __float_as_uint(pa1[0]);
            a[2] = __float_as_uint(pa0[4]);
            a[3] = __float_as_uint(pa1[4]);
            #pragma unroll
            for (int nf = 0; nf < 8; nf++) {
                const float* vb = sm + SM_V + (nf * 8 + g) * SSTR + kf * 8 + tig;
                mma8(O[nf], a,
                     __float_as_uint(vb[0]), __float_as_uint(vb[4]));
            }
        }

        // ---- diagonal value correction: O[l] += p_ll * (vd[l] - v[l]) ----
        if (diag && drawn) {
            __syncwarp();
            const float p0 = sm[SM_D + lr0];
            const float p1 = sm[SM_D + lr1];
            const float* vd0 = vd + hb + grow0 * RSTR;
            const float* vv0 = v  + hb + grow0 * RSTR;
            const float* vd1 = vd + hb + grow1 * RSTR;
            const float* vv1 = v  + hb + grow1 * RSTR;
            #pragma unroll
            for (int nf = 0; nf < 8; nf++) {
                const int c = nf * 8 + 2 * tig;
                const float2 a0 = *(const float2*)(vd0 + c);
                const float2 b0 = *(const float2*)(vv0 + c);
                const float2 a1 = *(const float2*)(vd1 + c);
                const float2 b1 = *(const float2*)(vv1 + c);
                O[nf][0] += p0 * (a0.x - b0.x);
                O[nf][1] += p0 * (a0.y - b0.y);
                O[nf][2] += p1 * (a1.x - b1.x);
                O[nf][3] += p1 * (a1.y - b1.y);
            }
        }
    }

    // ---- epilogue: normalize and store ----
    const float inv0 = 1.0f / rl0;
    const float inv1 = 1.0f / rl1;
    float* o0 = out + hb + grow0 * RSTR;
    float* o1 = out + hb + grow1 * RSTR;
    #pragma unroll
    for (int nf = 0; nf < 8; nf++) {
        const int c = nf * 8 + 2 * tig;
        *(float2*)(o0 + c) = make_float2(O[nf][0] * inv0, O[nf][1] * inv0);
        *(float2*)(o1 + c) = make_float2(O[nf][2] * inv1, O[nf][3] * inv1);
    }
}

extern "C" void kernel_launch(void* const* d_in, const int* in_sizes, int n_in,
                              void* d_out, int out_size)
{
    const float* q  = (const float*)d_in[0];
    const float* k  = (const float*)d_in[1];
    const float* v  = (const float*)d_in[2];
    const float* qd = (const float*)d_in[3];
    const float* kd = (const float*)d_in[4];
    const float* vd = (const float*)d_in[5];
    // d_in[6] = attn_mask (triu(k=1), handled analytically)
    // d_in[7] = history_len (fixed 512)
    float* out = (float*)d_out;

    cudaFuncSetAttribute(ftc_attn_tc,
                         cudaFuncAttributeMaxDynamicSharedMemorySize, SMEM_BYTES);
    dim3 grid(16, BB * HH);
    ftc_attn_tc<<<grid, 128, SMEM_BYTES>>>(q, k, v, qd, kd, vd, out);
}

// round 4
// speedup vs baseline: 2.9618x; 1.1810x over previous
#include <cuda_runtime.h>
#include <cstdint>

// Problem constants
#define BB   8
#define LL   1024
#define HH   8
#define EE   64
#define HIST 512
#define RSTR 512          // element stride between consecutive l (HH*EE)

#define SSTR 72           // smem row stride (72 % 32 == 8 -> conflict-free LDS.64 frags)
#define SM_K 0
#define SM_V (64*SSTR)
#define SM_D (2*64*SSTR)
#define SMEM_FLOATS (2*64*SSTR + 64)
#define SMEM_BYTES  (SMEM_FLOATS * 4)

static __device__ __forceinline__ uint32_t f2tf(float f) {
    uint32_t u;
    asm("cvt.rna.tf32.f32 %0, %1;" : "=r"(u) : "f"(f));
    return u;
}

static __device__ __forceinline__ void mma8(float* c, const uint32_t* a,
                                            uint32_t b0, uint32_t b1) {
    asm volatile("mma.sync.aligned.m16n8k8.row.col.f32.tf32.tf32.f32 "
                 "{%0,%1,%2,%3}, {%4,%5,%6,%7}, {%8,%9}, {%0,%1,%2,%3};"
                 : "+f"(c[0]), "+f"(c[1]), "+f"(c[2]), "+f"(c[3])
                 : "r"(a[0]), "r"(a[1]), "r"(a[2]), "r"(a[3]),
                   "r"(b0), "r"(b1));
}

// Logical-k permutation: k' = (e>>1) + (e&1)*4 within each 8-group.
// A-fragment slot k'=tig   -> natural col 2*tig
// A-fragment slot k'=tig+4 -> natural col 2*tig+1
// => B fragments are contiguous float2 loads from naturally-stored tiles,
//    and the PV A-fragment is a register permutation of the S accumulator.

__global__ __launch_bounds__(128, 3)
void ftc_attn_tc2(const float* __restrict__ q,  const float* __restrict__ k,
                  const float* __restrict__ v,  const float* __restrict__ qd,
                  const float* __restrict__ kd, const float* __restrict__ vd,
                  float* __restrict__ out)
{
    extern __shared__ float sm[];

    const int tid  = threadIdx.x;
    const int warp = tid >> 5;
    const int lane = tid & 31;
    const int g    = lane >> 2;     // groupID
    const int tig  = lane & 3;      // thread in group

    const int qt = 15 - blockIdx.x;       // big tiles first
    const int bh = blockIdx.y;
    const int b  = bh >> 3;
    const int h  = bh & 7;
    const int l0 = qt * 64;
    const bool drawn = (l0 >= HIST);
    const int hb = (b * LL * HH + h) * EE;

    // scale = 1/sqrt(64) * log2(e)  (exp2-based softmax)
    const float qscale = 0.125f * 1.4426950408889634f;

    const int lr0 = warp * 16 + g;
    const int lr1 = lr0 + 8;
    const int grow0 = l0 + lr0;
    const int grow1 = l0 + lr1;

    // ---- Q fragments (k'-permuted): natural cols {2tig, 2tig+1} ----
    const float* Qsrc = drawn ? qd : q;
    const float* q0p = Qsrc + hb + grow0 * RSTR;
    const float* q1p = Qsrc + hb + grow1 * RSTR;
    uint32_t qf[8][4];
    #pragma unroll
    for (int kf = 0; kf < 8; kf++) {
        const float2 t0 = *(const float2*)(q0p + kf * 8 + 2 * tig);
        const float2 t1 = *(const float2*)(q1p + kf * 8 + 2 * tig);
        qf[kf][0] = f2tf(t0.x * qscale);   // k'=tig,   row lr0
        qf[kf][1] = f2tf(t1.x * qscale);   // k'=tig,   row lr1
        qf[kf][2] = f2tf(t0.y * qscale);   // k'=tig+4, row lr0
        qf[kf][3] = f2tf(t1.y * qscale);   // k'=tig+4, row lr1
    }

    float O[8][4];
    #pragma unroll
    for (int nf = 0; nf < 8; nf++) {
        O[nf][0] = 0.f; O[nf][1] = 0.f; O[nf][2] = 0.f; O[nf][3] = 0.f;
    }
    float m0 = -1e30f, m1 = -1e30f;
    float rl0 = 0.f,  rl1 = 0.f;

    for (int st = 0; st <= qt; st++) {
        const int  s0   = st * 64;
        const bool diag = (st == qt);

        __syncthreads();   // previous tile's smem consumers done

        // ---- K tile -> Ks[s][e] natural (tf32-rounded), coalesced ----
        #pragma unroll
        for (int it = 0; it < 8; it++) {
            const int i  = it * 128 + tid;
            const int s  = i >> 4;
            const int e4 = (i & 15) * 4;
            const float4 t = *(const float4*)(k + hb + (s0 + s) * RSTR + e4);
            float* d = sm + SM_K + s * SSTR + e4;
            d[0] = __uint_as_float(f2tf(t.x));
            d[1] = __uint_as_float(f2tf(t.y));
            d[2] = __uint_as_float(f2tf(t.z));
            d[3] = __uint_as_float(f2tf(t.w));
        }
        // ---- V tile -> Vt[d][s] transposed (tf32-rounded) ----
        {
            const int s     = tid & 63;
            const int dbase = (tid >> 6) * 32;
            const float* vp = v + hb + (s0 + s) * RSTR + dbase;
            #pragma unroll
            for (int i = 0; i < 8; i++) {
                const float4 t = *(const float4*)(vp + i * 4);
                float* d = sm + SM_V + (dbase + i * 4) * SSTR + s;
                d[0*SSTR] = __uint_as_float(f2tf(t.x));
                d[1*SSTR] = __uint_as_float(f2tf(t.y));
                d[2*SSTR] = __uint_as_float(f2tf(t.z));
                d[3*SSTR] = __uint_as_float(f2tf(t.w));
            }
        }
        // ---- diagonal scores (drawn): sd[l] = dot(qd[l], kd[l]) * qscale ----
        if (diag && drawn) {
            const int lr  = tid >> 1;
            const int off = (tid & 1) * 32;
            const float* qp = qd + hb + (l0 + lr) * RSTR + off;
            const float* kp = kd + hb + (l0 + lr) * RSTR + off;
            float acc = 0.f;
            #pragma unroll
            for (int i = 0; i < 8; i++) {
                const float4 a = *(const float4*)(qp + i * 4);
                const float4 c = *(const float4*)(kp + i * 4);
                acc += a.x*c.x + a.y*c.y + a.z*c.z + a.w*c.w;
            }
            acc += __shfl_xor_sync(0xffffffffu, acc, 1);
            if (!(tid & 1)) sm[SM_D + lr] = acc * qscale;
        }
        __syncthreads();

        // ---- S = Q @ K^T via tensor cores (B frag = single LDS.64) ----
        float S[8][4];
        #pragma unroll
        for (int nf = 0; nf < 8; nf++) {
            S[nf][0] = 0.f; S[nf][1] = 0.f; S[nf][2] = 0.f; S[nf][3] = 0.f;
        }
        #pragma unroll
        for (int kf = 0; kf < 8; kf++) {
            #pragma unroll
            for (int nf = 0; nf < 8; nf++) {
                const float2 kb = *(const float2*)(sm + SM_K + (nf * 8 + g) * SSTR
                                                   + kf * 8 + 2 * tig);
                mma8(S[nf], qf[kf],
                     __float_as_uint(kb.x), __float_as_uint(kb.y));
            }
        }

        // ---- mask + diagonal override (diag tile only) ----
        if (diag) {
            #pragma unroll
            for (int nf = 0; nf < 8; nf++) {
                const int sc = s0 + nf * 8 + 2 * tig;
                if (sc     > grow0) S[nf][0] = -1e30f;
                if (sc + 1 > grow0) S[nf][1] = -1e30f;
                if (sc     > grow1) S[nf][2] = -1e30f;
                if (sc + 1 > grow1) S[nf][3] = -1e30f;
                if (drawn) {
                    if (sc     == grow0) S[nf][0] = sm[SM_D + lr0];
                    if (sc + 1 == grow0) S[nf][1] = sm[SM_D + lr0];
                    if (sc     == grow1) S[nf][2] = sm[SM_D + lr1];
                    if (sc + 1 == grow1) S[nf][3] = sm[SM_D + lr1];
                }
            }
        }

        // ---- online softmax (per-warp, exp2-based) ----
        float tm0 = -1e30f, tm1 = -1e30f;
        #pragma unroll
        for (int nf = 0; nf < 8; nf++) {
            tm0 = fmaxf(tm0, fmaxf(S[nf][0], S[nf][1]));
            tm1 = fmaxf(tm1, fmaxf(S[nf][2], S[nf][3]));
        }
        tm0 = fmaxf(tm0, __shfl_xor_sync(0xffffffffu, tm0, 1));
        tm0 = fmaxf(tm0, __shfl_xor_sync(0xffffffffu, tm0, 2));
        tm1 = fmaxf(tm1, __shfl_xor_sync(0xffffffffu, tm1, 1));
        tm1 = fmaxf(tm1, __shfl_xor_sync(0xffffffffu, tm1, 2));
        const float mn0 = fmaxf(m0, tm0);
        const float mn1 = fmaxf(m1, tm1);
        const float corr0 = exp2f(m0 - mn0);
        const float corr1 = exp2f(m1 - mn1);
        m0 = mn0; m1 = mn1;

        float sum0 = 0.f, sum1 = 0.f;
        #pragma unroll
        for (int nf = 0; nf < 8; nf++) {
            S[nf][0] = exp2f(S[nf][0] - mn0); sum0 += S[nf][0];
            S[nf][1] = exp2f(S[nf][1] - mn0); sum0 += S[nf][1];
            S[nf][2] = exp2f(S[nf][2] - mn1); sum1 += S[nf][2];
            S[nf][3] = exp2f(S[nf][3] - mn1); sum1 += S[nf][3];
        }
        sum0 += __shfl_xor_sync(0xffffffffu, sum0, 1);
        sum0 += __shfl_xor_sync(0xffffffffu, sum0, 2);
        sum1 += __shfl_xor_sync(0xffffffffu, sum1, 1);
        sum1 += __shfl_xor_sync(0xffffffffu, sum1, 2);
        rl0 = rl0 * corr0 + sum0;
        rl1 = rl1 * corr1 + sum1;

        #pragma unroll
        for (int nf = 0; nf < 8; nf++) {
            O[nf][0] *= corr0; O[nf][1] *= corr0;
            O[nf][2] *= corr1; O[nf][3] *= corr1;
        }

        // ---- capture diagonal p (fp32) for the value correction ----
        float pd0 = 0.f, pd1 = 0.f;
        if (diag && drawn) {
            #pragma unroll
            for (int nf = 0; nf < 8; nf++) {
                const int sc = s0 + nf * 8 + 2 * tig;
                if (sc     == grow0) pd0 = S[nf][0];
                if (sc + 1 == grow0) pd0 = S[nf][1];
                if (sc     == grow1) pd1 = S[nf][2];
                if (sc + 1 == grow1) pd1 = S[nf][3];
            }
            // row diag lives in exactly one lane's fragment; broadcast via max
            pd0 = fmaxf(pd0, __shfl_xor_sync(0xffffffffu, pd0, 1));
            pd0 = fmaxf(pd0, __shfl_xor_sync(0xffffffffu, pd0, 2));
            pd1 = fmaxf(pd1, __shfl_xor_sync(0xffffffffu, pd1, 1));
            pd1 = fmaxf(pd1, __shfl_xor_sync(0xffffffffu, pd1, 2));
        }

        // ---- O += P @ V : A frag is a register permutation of S (k'-trick) ----
        #pragma unroll
        for (int kf = 0; kf < 8; kf++) {
            uint32_t a[4];
            a[0] = f2tf(S[kf][0]);   // P[row lr0][k'=tig]   = natural col 2tig
            a[1] = f2tf(S[kf][2]);   // P[row lr1][k'=tig]
            a[2] = f2tf(S[kf][1]);   // P[row lr0][k'=tig+4] = natural col 2tig+1
            a[3] = f2tf(S[kf][3]);   // P[row lr1][k'=tig+4]
            #pragma unroll
            for (int nf = 0; nf < 8; nf++) {
                const float2 vb = *(const float2*)(sm + SM_V + (nf * 8 + g) * SSTR
                                                   + kf * 8 + 2 * tig);
                mma8(O[nf], a,
                     __float_as_uint(vb.x), __float_as_uint(vb.y));
            }
        }

        // ---- diagonal value correction: O[l] += p_ll * (vd[l] - v[l]) ----
        if (diag && drawn) {
            const float* vd0 = vd + hb + grow0 * RSTR;
            const float* vv0 = v  + hb + grow0 * RSTR;
            const float* vd1 = vd + hb + grow1 * RSTR;
            const float* vv1 = v  + hb + grow1 * RSTR;
            #pragma unroll
            for (int nf = 0; nf < 8; nf++) {
                const int c = nf * 8 + 2 * tig;
                const float2 a0 = *(const float2*)(vd0 + c);
                const float2 b0 = *(const float2*)(vv0 + c);
                const float2 a1 = *(const float2*)(vd1 + c);
                const float2 b1 = *(const float2*)(vv1 + c);
                O[nf][0] += pd0 * (a0.x - b0.x);
                O[nf][1] += pd0 * (a0.y - b0.y);
                O[nf][2] += pd1 * (a1.x - b1.x);
                O[nf][3] += pd1 * (a1.y - b1.y);
            }
        }
    }

    // ---- epilogue: normalize and store ----
    const float inv0 = 1.0f / rl0;
    const float inv1 = 1.0f / rl1;
    float* o0 = out + hb + grow0 * RSTR;
    float* o1 = out + hb + grow1 * RSTR;
    #pragma unroll
    for (int nf = 0; nf < 8; nf++) {
        const int c = nf * 8 + 2 * tig;
        *(float2*)(o0 + c) = make_float2(O[nf][0] * inv0, O[nf][1] * inv0);
        *(float2*)(o1 + c) = make_float2(O[nf][2] * inv1, O[nf][3] * inv1);
    }
}

extern "C" void kernel_launch(void* const* d_in, const int* in_sizes, int n_in,
                              void* d_out, int out_size)
{
    const float* q  = (const float*)d_in[0];
    const float* k  = (const float*)d_in[1];
    const float* v  = (const float*)d_in[2];
    const float* qd = (const float*)d_in[3];
    const float* kd = (const float*)d_in[4];
    const float* vd = (const float*)d_in[5];
    // d_in[6] = attn_mask (triu(k=1), handled analytically)
    // d_in[7] = history_len (fixed 512)
    float* out = (float*)d_out;

    cudaFuncSetAttribute(ftc_attn_tc2,
                         cudaFuncAttributeMaxDynamicSharedMemorySize, SMEM_BYTES);
    dim3 grid(16, BB * HH);
    ftc_attn_tc2<<<grid, 128, SMEM_BYTES>>>(q, k, v, qd, kd, vd, out);
}

// round 5
// speedup vs baseline: 3.7484x; 1.2656x over previous
#include <cuda_runtime.h>
#include <cuda_fp16.h>
#include <cstdint>

// Problem constants
#define BB   8
#define LL   1024
#define HH   8
#define EE   64
#define HIST 512
#define RSTR 512          // element stride between consecutive l (HH*EE)

#define KSTR 80           // half-elem row stride: 160B = 40 words -> 8-bank row shift,
#define VSTR 80           // half-warp LDS.64 phases tile all 32 banks exactly
#define SM_K 0
#define SM_V (64*KSTR)
#define SMH_TOTAL (2*64*KSTR)          // halves
#define SMEM_BYTES (SMH_TOTAL*2 + 64*4)

static __device__ __forceinline__ uint32_t packh2(float a, float b) {
    __half2 h = __floats2half2_rn(a, b);
    return reinterpret_cast<uint32_t&>(h);
}

static __device__ __forceinline__ void mma16(float* c, const uint32_t* a,
                                             uint32_t b0, uint32_t b1) {
    asm volatile("mma.sync.aligned.m16n8k16.row.col.f32.f16.f16.f32 "
                 "{%0,%1,%2,%3}, {%4,%5,%6,%7}, {%8,%9}, {%0,%1,%2,%3};"
                 : "+f"(c[0]), "+f"(c[1]), "+f"(c[2]), "+f"(c[3])
                 : "r"(a[0]), "r"(a[1]), "r"(a[2]), "r"(a[3]),
                   "r"(b0), "r"(b1));
}

// Logical-k permutation within each 16-group:
//   logical slot 2t+j   <-> natural col 4t+j       (j in {0,1})
//   logical slot 8+2t+j <-> natural col 4t+2+j
// => A frag regs = contiguous natural 4tig..4tig+3 (Q: one float4 per row per group)
// => QK B frag = one LDS.64 of naturally-stored K [s][e]
// => PV A frag = register packing of S accumulators (P never hits smem)
// => PV B frag = one LDS.64 of V^T with column permutation qcol(s)

__global__ __launch_bounds__(128, 3)
void ftc_attn_h16(const float* __restrict__ q,  const float* __restrict__ k,
                  const float* __restrict__ v,  const float* __restrict__ qd,
                  const float* __restrict__ kd, const float* __restrict__ vd,
                  float* __restrict__ out)
{
    extern __shared__ char smraw[];
    __half* smh = (__half*)smraw;
    float*  smd = (float*)(smraw + SMH_TOTAL*2);

    const int tid  = threadIdx.x;
    const int warp = tid >> 5;
    const int lane = tid & 31;
    const int g    = lane >> 2;     // groupID
    const int tig  = lane & 3;      // thread in group

    const int qt = 15 - blockIdx.x;       // big tiles first
    const int bh = blockIdx.y;
    const int b  = bh >> 3;
    const int h  = bh & 7;
    const int l0 = qt * 64;
    const bool drawn = (l0 >= HIST);
    const int hb = (b * LL * HH + h) * EE;

    // scale = 1/sqrt(64) * log2(e)  (exp2-based softmax)
    const float qscale = 0.125f * 1.4426950408889634f;

    const int lr0 = warp * 16 + g;
    const int lr1 = lr0 + 8;
    const int grow0 = l0 + lr0;
    const int grow1 = l0 + lr1;

    // ---- Q fragments: natural cols 16kf+4tig..+3, rows lr0/lr1, fp16 ----
    const float* Qsrc = drawn ? qd : q;
    const float* q0p = Qsrc + hb + grow0 * RSTR;
    const float* q1p = Qsrc + hb + grow1 * RSTR;
    uint32_t qf[4][4];
    #pragma unroll
    for (int kf = 0; kf < 4; kf++) {
        const float4 t0 = *(const float4*)(q0p + kf * 16 + 4 * tig);
        const float4 t1 = *(const float4*)(q1p + kf * 16 + 4 * tig);
        qf[kf][0] = packh2(t0.x * qscale, t0.y * qscale);  // row lr0, logical k 2tig,2tig+1
        qf[kf][1] = packh2(t1.x * qscale, t1.y * qscale);  // row lr1
        qf[kf][2] = packh2(t0.z * qscale, t0.w * qscale);  // row lr0, logical k 8+2tig,..
        qf[kf][3] = packh2(t1.z * qscale, t1.w * qscale);  // row lr1
    }

    float O[8][4];
    #pragma unroll
    for (int nf = 0; nf < 8; nf++) {
        O[nf][0] = 0.f; O[nf][1] = 0.f; O[nf][2] = 0.f; O[nf][3] = 0.f;
    }
    float m0 = -1e30f, m1 = -1e30f;
    float rl0 = 0.f,  rl1 = 0.f;

    // V^T column permutation data (per-thread constant)
    const int vs    = tid & 63;            // natural s this thread transposes
    const int vr    = vs & 15;
    const int qcol  = (vs & ~15) + ((vr >> 1) & 3) * 4 + ((vr >> 3) << 1) + (vr & 1);
    const int dbase = (tid >> 6) * 32;

    for (int st = 0; st <= qt; st++) {
        const int  s0   = st * 64;
        const bool diag = (st == qt);

        __syncthreads();   // previous tile's smem consumers done

        // ---- K tile -> Ks[s][e] natural, fp16, coalesced ----
        #pragma unroll
        for (int it = 0; it < 8; it++) {
            const int i  = it * 128 + tid;
            const int s  = i >> 4;
            const int e4 = (i & 15) * 4;
            const float4 t = *(const float4*)(k + hb + (s0 + s) * RSTR + e4);
            uint2 pk;
            pk.x = packh2(t.x, t.y);
            pk.y = packh2(t.z, t.w);
            *(uint2*)(smh + SM_K + s * KSTR + e4) = pk;
        }
        // ---- V tile -> Vt[d][qcol(s)] transposed, fp16 ----
        {
            const float* vp = v + hb + (s0 + vs) * RSTR + dbase;
            #pragma unroll
            for (int i = 0; i < 8; i++) {
                const float4 t = *(const float4*)(vp + i * 4);
                __half* d = smh + SM_V + (dbase + i * 4) * VSTR + qcol;
                d[0*VSTR] = __float2half_rn(t.x);
                d[1*VSTR] = __float2half_rn(t.y);
                d[2*VSTR] = __float2half_rn(t.z);
                d[3*VSTR] = __float2half_rn(t.w);
            }
        }
        // ---- diagonal scores (drawn): sd[l] = dot(qd[l], kd[l]) * qscale ----
        if (diag && drawn) {
            const int lr  = tid >> 1;
            const int off = (tid & 1) * 32;
            const float* qp = qd + hb + (l0 + lr) * RSTR + off;
            const float* kp = kd + hb + (l0 + lr) * RSTR + off;
            float acc = 0.f;
            #pragma unroll
            for (int i = 0; i < 8; i++) {
                const float4 a = *(const float4*)(qp + i * 4);
                const float4 c = *(const float4*)(kp + i * 4);
                acc += a.x*c.x + a.y*c.y + a.z*c.z + a.w*c.w;
            }
            acc += __shfl_xor_sync(0xffffffffu, acc, 1);
            if (!(tid & 1)) smd[lr] = acc * qscale;
        }
        __syncthreads();

        // ---- S = Q @ K^T via fp16 tensor cores (B frag = one LDS.64) ----
        float S[8][4];
        #pragma unroll
        for (int nf = 0; nf < 8; nf++) {
            S[nf][0] = 0.f; S[nf][1] = 0.f; S[nf][2] = 0.f; S[nf][3] = 0.f;
        }
        #pragma unroll
        for (int kf = 0; kf < 4; kf++) {
            #pragma unroll
            for (int nf = 0; nf < 8; nf++) {
                const uint2 kb = *(const uint2*)(smh + SM_K + (nf * 8 + g) * KSTR
                                                 + kf * 16 + 4 * tig);
                mma16(S[nf], qf[kf], kb.x, kb.y);
            }
        }

        // ---- mask + diagonal override (diag tile only) ----
        // S[nf] c0,c1 correspond to natural s columns s0+8nf+2tig, +1 (rows lr0/lr1)
        if (diag) {
            #pragma unroll
            for (int nf = 0; nf < 8; nf++) {
                const int sc = s0 + nf * 8 + 2 * tig;
                if (sc     > grow0) S[nf][0] = -1e30f;
                if (sc + 1 > grow0) S[nf][1] = -1e30f;
                if (sc     > grow1) S[nf][2] = -1e30f;
                if (sc + 1 > grow1) S[nf][3] = -1e30f;
                if (drawn) {
                    if (sc     == grow0) S[nf][0] = smd[lr0];
                    if (sc + 1 == grow0) S[nf][1] = smd[lr0];
                    if (sc     == grow1) S[nf][2] = smd[lr1];
                    if (sc + 1 == grow1) S[nf][3] = smd[lr1];
                }
            }
        }

        // ---- online softmax (per-warp, exp2-based) ----
        float tm0 = -1e30f, tm1 = -1e30f;
        #pragma unroll
        for (int nf = 0; nf < 8; nf++) {
            tm0 = fmaxf(tm0, fmaxf(S[nf][0], S[nf][1]));
            tm1 = fmaxf(tm1, fmaxf(S[nf][2], S[nf][3]));
        }
        tm0 = fmaxf(tm0, __shfl_xor_sync(0xffffffffu, tm0, 1));
        tm0 = fmaxf(tm0, __shfl_xor_sync(0xffffffffu, tm0, 2));
        tm1 = fmaxf(tm1, __shfl_xor_sync(0xffffffffu, tm1, 1));
        tm1 = fmaxf(tm1, __shfl_xor_sync(0xffffffffu, tm1, 2));
        const float mn0 = fmaxf(m0, tm0);
        const float mn1 = fmaxf(m1, tm1);
        const float corr0 = exp2f(m0 - mn0);
        const float corr1 = exp2f(m1 - mn1);
        m0 = mn0; m1 = mn1;

        float sum0 = 0.f, sum1 = 0.f;
        #pragma unroll
        for (int nf = 0; nf < 8; nf++) {
            S[nf][0] = exp2f(S[nf][0] - mn0); sum0 += S[nf][0];
            S[nf][1] = exp2f(S[nf][1] - mn0); sum0 += S[nf][1];
            S[nf][2] = exp2f(S[nf][2] - mn1); sum1 += S[nf][2];
            S[nf][3] = exp2f(S[nf][3] - mn1); sum1 += S[nf][3];
        }
        sum0 += __shfl_xor_sync(0xffffffffu, sum0, 1);
        sum0 += __shfl_xor_sync(0xffffffffu, sum0, 2);
        sum1 += __shfl_xor_sync(0xffffffffu, sum1, 1);
        sum1 += __shfl_xor_sync(0xffffffffu, sum1, 2);
        rl0 = rl0 * corr0 + sum0;
        rl1 = rl1 * corr1 + sum1;

        #pragma unroll
        for (int nf = 0; nf < 8; nf++) {
            O[nf][0] *= corr0; O[nf][1] *= corr0;
            O[nf][2] *= corr1; O[nf][3] *= corr1;
        }

        // ---- capture diagonal p (fp32) for the value correction ----
        float pd0 = 0.f, pd1 = 0.f;
        if (diag && drawn) {
            #pragma unroll
            for (int nf = 0; nf < 8; nf++) {
                const int sc = s0 + nf * 8 + 2 * tig;
                if (sc     == grow0) pd0 = S[nf][0];
                if (sc + 1 == grow0) pd0 = S[nf][1];
                if (sc     == grow1) pd1 = S[nf][2];
                if (sc + 1 == grow1) pd1 = S[nf][3];
            }
            pd0 = fmaxf(pd0, __shfl_xor_sync(0xffffffffu, pd0, 1));
            pd0 = fmaxf(pd0, __shfl_xor_sync(0xffffffffu, pd0, 2));
            pd1 = fmaxf(pd1, __shfl_xor_sync(0xffffffffu, pd1, 1));
            pd1 = fmaxf(pd1, __shfl_xor_sync(0xffffffffu, pd1, 2));
        }

        // ---- O += P @ V : A frag = register packing of S (k16 group m = S[2m],S[2m+1]) ----
        #pragma unroll
        for (int m = 0; m < 4; m++) {
            uint32_t a[4];
            a[0] = packh2(S[2*m  ][0], S[2*m  ][1]);  // row lr0, logical k 2tig,2tig+1
            a[1] = packh2(S[2*m  ][2], S[2*m  ][3]);  // row lr1
            a[2] = packh2(S[2*m+1][0], S[2*m+1][1]);  // row lr0, logical k 8+2tig,..
            a[3] = packh2(S[2*m+1][2], S[2*m+1][3]);  // row lr1
            #pragma unroll
            for (int nf = 0; nf < 8; nf++) {
                const uint2 vb = *(const uint2*)(smh + SM_V + (nf * 8 + g) * VSTR
                                                 + m * 16 + 4 * tig);
                mma16(O[nf], a, vb.x, vb.y);
            }
        }

        // ---- diagonal value correction: O[l] += p_ll * (vd[l] - v[l]) ----
        if (diag && drawn) {
            const float* vd0 = vd + hb + grow0 * RSTR;
            const float* vv0 = v  + hb + grow0 * RSTR;
            const float* vd1 = vd + hb + grow1 * RSTR;
            const float* vv1 = v  + hb + grow1 * RSTR;
            #pragma unroll
            for (int nf = 0; nf < 8; nf++) {
                const int c = nf * 8 + 2 * tig;
                const float2 a0 = *(const float2*)(vd0 + c);
                const float2 b0 = *(const float2*)(vv0 + c);
                const float2 a1 = *(const float2*)(vd1 + c);
                const float2 b1 = *(const float2*)(vv1 + c);
                O[nf][0] += pd0 * (a0.x - b0.x);
                O[nf][1] += pd0 * (a0.y - b0.y);
                O[nf][2] += pd1 * (a1.x - b1.x);
                O[nf][3] += pd1 * (a1.y - b1.y);
            }
        }
    }

    // ---- epilogue: normalize and store ----
    const float inv0 = 1.0f / rl0;
    const float inv1 = 1.0f / rl1;
    float* o0 = out + hb + grow0 * RSTR;
    float* o1 = out + hb + grow1 * RSTR;
    #pragma unroll
    for (int nf = 0; nf < 8; nf++) {
        const int c = nf * 8 + 2 * tig;
        *(float2*)(o0 + c) = make_float2(O[nf][0] * inv0, O[nf][1] * inv0);
        *(float2*)(o1 + c) = make_float2(O[nf][2] * inv1, O[nf][3] * inv1);
    }
}

extern "C" void kernel_launch(void* const* d_in, const int* in_sizes, int n_in,
                              void* d_out, int out_size)
{
    const float* q  = (const float*)d_in[0];
    const float* k  = (const float*)d_in[1];
    const float* v  = (const float*)d_in[2];
    const float* qd = (const float*)d_in[3];
    const float* kd = (const float*)d_in[4];
    const float* vd = (const float*)d_in[5];
    // d_in[6] = attn_mask (triu(k=1), handled analytically)
    // d_in[7] = history_len (fixed 512)
    float* out = (float*)d_out;

    cudaFuncSetAttribute(ftc_attn_h16,
                         cudaFuncAttributeMaxDynamicSharedMemorySize, SMEM_BYTES);
    dim3 grid(16, BB * HH);
    ftc_attn_h16<<<grid, 128, SMEM_BYTES>>>(q, k, v, qd, kd, vd, out);
}

// round 6
// speedup vs baseline: 5.5792x; 1.4884x over previous
#include <cuda_runtime.h>
#include <cuda_fp16.h>
#include <cstdint>

// Problem constants
#define BB   8
#define LL   1024
#define HH   8
#define EE   64
#define HIST 512
#define RSTR 512           // element stride between consecutive l (HH*EE)
#define NELEM (BB*LL*HH*EE)

// fp16 staging buffers (pre-converted once per launch)
__device__ __half g_qh[NELEM];   // q_eff * qscale, fp16
__device__ __half g_kh[NELEM];   // k, fp16
__device__ __half g_vh[NELEM];   // v, fp16

#define KSTR 80            // K smem row stride (halves): LDS.64 frag conflict-free
#define VSTR 72            // V smem row stride (halves): ldmatrix rows hit 2-wf minimum
#define STAGEH (64*KSTR + 64*VSTR)     // halves per pipeline stage (9728)
#define SMEM_BYTES (2*STAGEH*2 + 64*4) // 2 stages + 64-float diag buffer

static __device__ __forceinline__ uint32_t packh2(float a, float b) {
    __half2 h = __floats2half2_rn(a, b);
    return reinterpret_cast<uint32_t&>(h);
}

static __device__ __forceinline__ void mma16(float* c, const uint32_t* a,
                                             uint32_t b0, uint32_t b1) {
    asm volatile("mma.sync.aligned.m16n8k16.row.col.f32.f16.f16.f32 "
                 "{%0,%1,%2,%3}, {%4,%5,%6,%7}, {%8,%9}, {%0,%1,%2,%3};"
                 : "+f"(c[0]), "+f"(c[1]), "+f"(c[2]), "+f"(c[3])
                 : "r"(a[0]), "r"(a[1]), "r"(a[2]), "r"(a[3]),
                   "r"(b0), "r"(b1));
}

static __device__ __forceinline__ void ldsm4t(uint32_t& r0, uint32_t& r1,
                                              uint32_t& r2, uint32_t& r3,
                                              uint32_t addr) {
    asm volatile("ldmatrix.sync.aligned.m8n8.x4.trans.shared.b16 {%0,%1,%2,%3}, [%4];"
                 : "=r"(r0), "=r"(r1), "=r"(r2), "=r"(r3) : "r"(addr));
}

#define CPA16(dst, src) \
    asm volatile("cp.async.ca.shared.global [%0], [%1], 16;" :: "r"(dst), "l"(src))
#define CPCOMMIT() asm volatile("cp.async.commit_group;")
#define CPWAIT1()  asm volatile("cp.async.wait_group 1;")

static __device__ __forceinline__ uint32_t smem_u32(const void* p) {
    uint32_t a;
    asm("{ .reg .u64 t; cvta.to.shared.u64 t, %1; cvt.u32.u64 %0, t; }"
        : "=r"(a) : "l"(p));
    return a;
}

// ---------------- pre-pass: fp32 -> fp16 (q select + scale folded) ----------------
__global__ void prep_kernel(const float* __restrict__ q, const float* __restrict__ k,
                            const float* __restrict__ v, const float* __restrict__ qd)
{
    const float qscale = 0.125f * 1.4426950408889634f;   // 1/sqrt(E) * log2(e)
    const int i4 = blockIdx.x * blockDim.x + threadIdx.x;  // float4 index
    const int e0 = i4 * 4;
    const int l  = (e0 >> 9) & (LL - 1);                   // e0 / (H*E) mod L
    const float4 tq = (l < HIST) ? *(const float4*)(q + e0)
                                 : *(const float4*)(qd + e0);
    uint2 oq;
    oq.x = packh2(tq.x * qscale, tq.y * qscale);
    oq.y = packh2(tq.z * qscale, tq.w * qscale);
    *(uint2*)(g_qh + e0) = oq;
    const float4 tk = *(const float4*)(k + e0);
    uint2 ok; ok.x = packh2(tk.x, tk.y); ok.y = packh2(tk.z, tk.w);
    *(uint2*)(g_kh + e0) = ok;
    const float4 tv = *(const float4*)(v + e0);
    uint2 ov; ov.x = packh2(tv.x, tv.y); ov.y = packh2(tv.z, tv.w);
    *(uint2*)(g_vh + e0) = ov;
}

// ---------------- main attention kernel ----------------
__global__ __launch_bounds__(128, 3)
void ftc_attn_cp(const float* __restrict__ qd, const float* __restrict__ kd,
                 const float* __restrict__ v,  const float* __restrict__ vd,
                 float* __restrict__ out)
{
    extern __shared__ __align__(16) char smraw[];
    __half* smh = (__half*)smraw;
    float*  smd = (float*)(smraw + 2 * STAGEH * 2);
    const uint32_t smb = smem_u32(smraw);

    const int tid  = threadIdx.x;
    const int warp = tid >> 5;
    const int lane = tid & 31;
    const int g    = lane >> 2;
    const int tig  = lane & 3;

    const int qt = 15 - blockIdx.x;       // big tiles first
    const int bh = blockIdx.y;
    const int b  = bh >> 3;
    const int h  = bh & 7;
    const int l0 = qt * 64;
    const bool drawn = (l0 >= HIST);
    const int hb = (b * LL * HH + h) * EE;

    const float qscale = 0.125f * 1.4426950408889634f;

    const int lr0 = warp * 16 + g;
    const int lr1 = lr0 + 8;
    const int grow0 = l0 + lr0;
    const int grow1 = l0 + lr1;

    // ldmatrix lane constants (V trans tiles)
    const int sbase  = ((lane >> 3) & 1) * 8 + (lane & 7);
    const int dbase8 = (lane >> 4) * 8;

    // ---- Q fragments from pre-converted fp16 (scale already folded) ----
    const __half* q0p = g_qh + hb + grow0 * RSTR;
    const __half* q1p = g_qh + hb + grow1 * RSTR;
    uint32_t qf[4][4];
    #pragma unroll
    for (int kf = 0; kf < 4; kf++) {
        const uint2 u0 = *(const uint2*)(q0p + kf * 16 + 4 * tig);
        const uint2 u1 = *(const uint2*)(q1p + kf * 16 + 4 * tig);
        qf[kf][0] = u0.x;   // row lr0, low-k pair
        qf[kf][1] = u1.x;   // row lr1, low-k pair
        qf[kf][2] = u0.y;   // row lr0, high-k pair
        qf[kf][3] = u1.y;   // row lr1, high-k pair
    }

    float O[8][4];
    #pragma unroll
    for (int nf = 0; nf < 8; nf++) {
        O[nf][0] = 0.f; O[nf][1] = 0.f; O[nf][2] = 0.f; O[nf][3] = 0.f;
    }
    float m0 = -1e30f, m1 = -1e30f;
    float rl0 = 0.f,  rl1 = 0.f;

    // ---- cp.async tile loader (K: 160B rows, V: 144B rows) ----
    auto load_tile = [&](int s0, int stage) {
        const uint32_t kbase = smb + stage * (STAGEH * 2);
        const uint32_t vbase = kbase + 64 * KSTR * 2;
        #pragma unroll
        for (int i = 0; i < 4; i++) {
            const int idx = tid + i * 128;
            const int s = idx >> 3, c = idx & 7;
            CPA16(kbase + s * 160 + c * 16, g_kh + hb + (s0 + s) * RSTR + c * 8);
        }
        #pragma unroll
        for (int i = 0; i < 4; i++) {
            const int idx = tid + i * 128;
            const int s = idx >> 3, c = idx & 7;
            CPA16(vbase + s * 144 + c * 16, g_vh + hb + (s0 + s) * RSTR + c * 8);
        }
    };

    load_tile(0, 0);
    CPCOMMIT();

    for (int st = 0; st <= qt; st++) {
        const int  s0   = st * 64;
        const bool diag = (st == qt);

        if (st < qt) load_tile(s0 + 64, (st + 1) & 1);
        CPCOMMIT();
        CPWAIT1();          // tile st resident; tile st+1 in flight

        // ---- diagonal scores (drawn): sd[l] = dot(qd[l], kd[l]) * qscale ----
        if (diag && drawn) {
            const int lr  = tid >> 1;
            const int off = (tid & 1) * 32;
            const float* qp = qd + hb + (l0 + lr) * RSTR + off;
            const float* kp = kd + hb + (l0 + lr) * RSTR + off;
            float acc = 0.f;
            #pragma unroll
            for (int i = 0; i < 8; i++) {
                const float4 a = *(const float4*)(qp + i * 4);
                const float4 c = *(const float4*)(kp + i * 4);
                acc += a.x*c.x + a.y*c.y + a.z*c.z + a.w*c.w;
            }
            acc += __shfl_xor_sync(0xffffffffu, acc, 1);
            if (!(tid & 1)) smd[lr] = acc * qscale;
        }
        __syncthreads();

        const __half*  Ks = smh + (st & 1) * STAGEH;
        const uint32_t Vb = smb + ((st & 1) * STAGEH + 64 * KSTR) * 2;

        // ---- S = Q @ K^T (fp16 mma, B frag = one LDS.64) ----
        float S[8][4];
        #pragma unroll
        for (int nf = 0; nf < 8; nf++) {
            S[nf][0] = 0.f; S[nf][1] = 0.f; S[nf][2] = 0.f; S[nf][3] = 0.f;
        }
        #pragma unroll
        for (int kf = 0; kf < 4; kf++) {
            #pragma unroll
            for (int nf = 0; nf < 8; nf++) {
                const uint2 kb = *(const uint2*)(Ks + (nf * 8 + g) * KSTR
                                                 + kf * 16 + 4 * tig);
                mma16(S[nf], qf[kf], kb.x, kb.y);
            }
        }

        // ---- mask + diagonal override (diag tile only) ----
        if (diag) {
            #pragma unroll
            for (int nf = 0; nf < 8; nf++) {
                const int sc = s0 + nf * 8 + 2 * tig;
                if (sc     > grow0) S[nf][0] = -1e30f;
                if (sc + 1 > grow0) S[nf][1] = -1e30f;
                if (sc     > grow1) S[nf][2] = -1e30f;
                if (sc + 1 > grow1) S[nf][3] = -1e30f;
                if (drawn) {
                    if (sc     == grow0) S[nf][0] = smd[lr0];
                    if (sc + 1 == grow0) S[nf][1] = smd[lr0];
                    if (sc     == grow1) S[nf][2] = smd[lr1];
                    if (sc + 1 == grow1) S[nf][3] = smd[lr1];
                }
            }
        }

        // ---- online softmax (per-warp, exp2-based) ----
        float tm0 = -1e30f, tm1 = -1e30f;
        #pragma unroll
        for (int nf = 0; nf < 8; nf++) {
            tm0 = fmaxf(tm0, fmaxf(S[nf][0], S[nf][1]));
            tm1 = fmaxf(tm1, fmaxf(S[nf][2], S[nf][3]));
        }
        tm0 = fmaxf(tm0, __shfl_xor_sync(0xffffffffu, tm0, 1));
        tm0 = fmaxf(tm0, __shfl_xor_sync(0xffffffffu, tm0, 2));
        tm1 = fmaxf(tm1, __shfl_xor_sync(0xffffffffu, tm1, 1));
        tm1 = fmaxf(tm1, __shfl_xor_sync(0xffffffffu, tm1, 2));
        const float mn0 = fmaxf(m0, tm0);
        const float mn1 = fmaxf(m1, tm1);
        const float corr0 = exp2f(m0 - mn0);
        const float corr1 = exp2f(m1 - mn1);
        m0 = mn0; m1 = mn1;

        float sum0 = 0.f, sum1 = 0.f;
        #pragma unroll
        for (int nf = 0; nf < 8; nf++) {
            S[nf][0] = exp2f(S[nf][0] - mn0); sum0 += S[nf][0];
            S[nf][1] = exp2f(S[nf][1] - mn0); sum0 += S[nf][1];
            S[nf][2] = exp2f(S[nf][2] - mn1); sum1 += S[nf][2];
            S[nf][3] = exp2f(S[nf][3] - mn1); sum1 += S[nf][3];
        }
        sum0 += __shfl_xor_sync(0xffffffffu, sum0, 1);
        sum0 += __shfl_xor_sync(0xffffffffu, sum0, 2);
        sum1 += __shfl_xor_sync(0xffffffffu, sum1, 1);
        sum1 += __shfl_xor_sync(0xffffffffu, sum1, 2);
        rl0 = rl0 * corr0 + sum0;
        rl1 = rl1 * corr1 + sum1;

        #pragma unroll
        for (int nf = 0; nf < 8; nf++) {
            O[nf][0] *= corr0; O[nf][1] *= corr0;
            O[nf][2] *= corr1; O[nf][3] *= corr1;
        }

        // ---- capture diagonal p (fp32) for the value correction ----
        float pd0 = 0.f, pd1 = 0.f;
        if (diag && drawn) {
            #pragma unroll
            for (int nf = 0; nf < 8; nf++) {
                const int sc = s0 + nf * 8 + 2 * tig;
                if (sc     == grow0) pd0 = S[nf][0];
                if (sc + 1 == grow0) pd0 = S[nf][1];
                if (sc     == grow1) pd1 = S[nf][2];
                if (sc + 1 == grow1) pd1 = S[nf][3];
            }
            pd0 = fmaxf(pd0, __shfl_xor_sync(0xffffffffu, pd0, 1));
            pd0 = fmaxf(pd0, __shfl_xor_sync(0xffffffffu, pd0, 2));
            pd1 = fmaxf(pd1, __shfl_xor_sync(0xffffffffu, pd1, 1));
            pd1 = fmaxf(pd1, __shfl_xor_sync(0xffffffffu, pd1, 2));
        }

        // ---- O += P @ V : A = register packing of S, B via ldmatrix.x4.trans ----
        #pragma unroll
        for (int m = 0; m < 4; m++) {
            uint32_t a[4];
            a[0] = packh2(S[2*m  ][0], S[2*m  ][1]);
            a[1] = packh2(S[2*m  ][2], S[2*m  ][3]);
            a[2] = packh2(S[2*m+1][0], S[2*m+1][1]);
            a[3] = packh2(S[2*m+1][2], S[2*m+1][3]);
            #pragma unroll
            for (int p = 0; p < 4; p++) {
                uint32_t r0, r1, r2, r3;
                ldsm4t(r0, r1, r2, r3,
                       Vb + ((16*m + sbase) * VSTR + 16*p + dbase8) * 2);
                mma16(O[2*p  ], a, r0, r1);
                mma16(O[2*p+1], a, r2, r3);
            }
        }

        // ---- diagonal value correction: O[l] += p_ll * (vd[l] - v[l]) ----
        if (diag && drawn) {
            const float* vd0 = vd + hb + grow0 * RSTR;
            const float* vv0 = v  + hb + grow0 * RSTR;
            const float* vd1 = vd + hb + grow1 * RSTR;
            const float* vv1 = v  + hb + grow1 * RSTR;
            #pragma unroll
            for (int nf = 0; nf < 8; nf++) {
                const int c = nf * 8 + 2 * tig;
                const float2 a0 = *(const float2*)(vd0 + c);
                const float2 b0 = *(const float2*)(vv0 + c);
                const float2 a1 = *(const float2*)(vd1 + c);
                const float2 b1 = *(const float2*)(vv1 + c);
                O[nf][0] += pd0 * (a0.x - b0.x);
                O[nf][1] += pd0 * (a0.y - b0.y);
                O[nf][2] += pd1 * (a1.x - b1.x);
                O[nf][3] += pd1 * (a1.y - b1.y);
            }
        }
        __syncthreads();   // all frag reads done before buffer reuse
    }

    // ---- epilogue: normalize and store ----
    const float inv0 = 1.0f / rl0;
    const float inv1 = 1.0f / rl1;
    float* o0 = out + hb + grow0 * RSTR;
    float* o1 = out + hb + grow1 * RSTR;
    #pragma unroll
    for (int nf = 0; nf < 8; nf++) {
        const int c = nf * 8 + 2 * tig;
        *(float2*)(o0 + c) = make_float2(O[nf][0] * inv0, O[nf][1] * inv0);
        *(float2*)(o1 + c) = make_float2(O[nf][2] * inv1, O[nf][3] * inv1);
    }
}

extern "C" void kernel_launch(void* const* d_in, const int* in_sizes, int n_in,
                              void* d_out, int out_size)
{
    const float* q  = (const float*)d_in[0];
    const float* k  = (const float*)d_in[1];
    const float* v  = (const float*)d_in[2];
    const float* qd = (const float*)d_in[3];
    const float* kd = (const float*)d_in[4];
    const float* vd = (const float*)d_in[5];
    // d_in[6] = attn_mask (triu(k=1), handled analytically)
    // d_in[7] = history_len (fixed 512)
    float* out = (float*)d_out;

    prep_kernel<<<NELEM / 4 / 256, 256>>>(q, k, v, qd);

    cudaFuncSetAttribute(ftc_attn_cp,
                         cudaFuncAttributeMaxDynamicSharedMemorySize, SMEM_BYTES);
    dim3 grid(16, BB * HH);
    ftc_attn_cp<<<grid, 128, SMEM_BYTES>>>(qd, kd, v, vd, out);
}